// round 9
// baseline (speedup 1.0000x reference)
#include <cuda_runtime.h>
#include <cuda_fp16.h>
#include <math.h>
#include <stdint.h>

// ---------------------------------------------------------------- constants
#define NB     16
#define CC     512
#define HWP    6144            // 64*96
#define WW     96
#define PX_TILE 128            // pixels per CTA
#define TILES_PER_IMG 48       // 6144/128
#define NKT    32              // 32 k-tiles of 16 = K 512
#define NTILES 7               // 7 n-tiles of 8 = 56 cols (54 real)
#define STAGES 5
#define ROWW   132             // floats per smem row (128 px + 4 pad)
#define STAGE_FLOATS (16 * ROWW)            // 2112
#define STAGE_BYTES  (STAGE_FLOATS * 4)     // 8448

// Output layout (floats): [rpn_loc | rpn_score | rpn_fg | anchor]
#define SC_BASE   3538944
#define FG_BASE   5308416
#define ANCH_BASE 6193152

// B fragments (fp16): [ktile(32)][lane(32)][16 u32 (7 ntiles*2 + pad)]
__device__ uint32_t g_bfrag[NKT * 32 * 16];   // 64 KB
__device__ float g_bias[64];

// ---------------------------------------------------------------- helpers
__device__ __forceinline__ uint32_t smem_u32(const void* p) {
    uint32_t a;
    asm("{ .reg .u64 t; cvta.to.shared.u64 t, %1; cvt.u32.u64 %0, t; }"
        : "=r"(a) : "l"(p));
    return a;
}

#define MMA16816(c, a, b0, b1)                                                \
    asm volatile("mma.sync.aligned.m16n8k16.row.col.f32.f16.f16.f32 "         \
        "{%0,%1,%2,%3}, {%4,%5,%6,%7}, {%8,%9}, {%0,%1,%2,%3};"               \
        : "+f"((c)[0]), "+f"((c)[1]), "+f"((c)[2]), "+f"((c)[3])              \
        : "r"((a)[0]), "r"((a)[1]), "r"((a)[2]), "r"((a)[3]),                 \
          "r"(b0), "r"(b1))

#define CVT2(d, flo, fhi)                                                     \
    asm("cvt.rn.f16x2.f32 %0, %1, %2;" : "=r"(d) : "f"(fhi), "f"(flo))

// issue one stage: this thread copies rows {wid, wid+8}, 16B at lane*16
#define ISSUE_P(SRC, D0, D1)                                                  \
    asm volatile("cp.async.ca.shared.global [%0], [%1], 16;\n\t"              \
                 "cp.async.ca.shared.global [%2], [%3], 16;\n\t"              \
                 "cp.async.commit_group;"                                     \
        :: "r"(D0), "l"(SRC), "r"(D1), "l"((SRC) + 8 * HWP) : "memory")

// ---------------------------------------------------------------- helper kernel
// Fused: B-fragment bake (fp16) + bias + anchors. 2 launches/call total.
__global__ void pack_w_kernel(const float* __restrict__ loc_w,
                              const float* __restrict__ loc_b,
                              const float* __restrict__ score_w,
                              const float* __restrict__ score_b,
                              float* __restrict__ out_anch) {
    int i = blockIdx.x * blockDim.x + threadIdx.x;

    // ---- B fragments: 32*32*8 = 8192 slots
    if (i < 8192) {
        int kt   = i >> 8;           // ktile 0..31
        int lane = (i >> 3) & 31;
        int nts  = i & 7;            // ntile slot (7 = zero pad)
        int o    = nts * 8 + (lane >> 2);
        int k0   = kt * 16 + 2 * (lane & 3);

        float w[4];
        #pragma unroll
        for (int q = 0; q < 4; q++) {
            int c = k0 + (q & 1) + (q >> 1) * 8;
            float v = 0.0f;
            if (o < 36)       v = loc_w[o * CC + c];
            else if (o < 54)  v = score_w[(o - 36) * CC + c];
            w[q] = v;
        }
        unsigned short u[4];
        #pragma unroll
        for (int q = 0; q < 4; q++)
            u[q] = __half_as_ushort(__float2half_rn(w[q]));
        int frag = kt * 32 + lane;
        g_bfrag[frag * 16 + nts * 2]     = (uint32_t)u[0] | ((uint32_t)u[1] << 16);
        g_bfrag[frag * 16 + nts * 2 + 1] = (uint32_t)u[2] | ((uint32_t)u[3] << 16);
    }

    // ---- bias
    if (i < 64) {
        float b = 0.0f;
        if (i < 36)       b = loc_b[i];
        else if (i < 54)  b = score_b[i - 36];
        g_bias[i] = b;
    }

    // ---- anchors
    if (i < HWP * 9) {
        int hw = i / 9, a = i % 9;
        int hy = hw / WW, wx = hw % WW;
        const double ratios[3] = {0.5, 1.0, 2.0};
        const double scales[3] = {8.0, 16.0, 32.0};
        double r = ratios[a / 3];
        double s = scales[a % 3];
        double ha = 16.0 * s * sqrt(r);
        double wa = 16.0 * s * sqrt(1.0 / r);
        float sy = (float)(hy * 16);
        float sx = (float)(wx * 16);
        float4 v;
        v.x = sy + (float)(8.0 - ha * 0.5);
        v.y = sx + (float)(8.0 - wa * 0.5);
        v.z = sy + (float)(8.0 + ha * 0.5);
        v.w = sx + (float)(8.0 + wa * 0.5);
        reinterpret_cast<float4*>(out_anch)[i] = v;
    }
}

// ---------------------------------------------------------------- main
// CTA = 128 px x 56 outs, 256 threads / 8 warps, warp -> 16 px (1 m-tile).
// cp.async 5-stage SMEM ring (fp32, padded rows), 4 stages in flight.
// Consume: 8 conflict-free LDS.32 -> cvt fp16 -> 7 HMMA per ktile per warp.
__global__ __launch_bounds__(256, 3)
void rpn_hmma_kernel(const float* __restrict__ x, float* __restrict__ out) {
    __shared__ __align__(16) float xs[STAGES * STAGE_FLOATS];  // 42,240 B

    const int tid  = threadIdx.x;
    const int lane = tid & 31;
    const int wid  = tid >> 5;
    const int b    = blockIdx.x;
    const int n    = b / TILES_PER_IMG;
    const int px0  = (b % TILES_PER_IMG) * PX_TILE;

    const float* xn = x + (size_t)n * CC * HWP + px0;

    // producer: thread copies rows {wid, wid+8} of each stage, 16B at lane*16
    const uint32_t xs_u = smem_u32(xs);
    const uint32_t d0 = xs_u + (uint32_t)(wid * ROWW + lane * 4) * 4;
    const uint32_t d1 = d0 + 8 * ROWW * 4;
    const float* psrc = xn + (size_t)wid * HWP + lane * 4;

    // consumer: lane reads ch = 2*(lane&3)+{0,1,8,9}, px = wid*16+(lane>>2)+{0,8}
    const float* cbase = xs + (2 * (lane & 3)) * ROWW + wid * 16 + (lane >> 2);

    float acc[NTILES][4];
    #pragma unroll
    for (int nt = 0; nt < NTILES; nt++)
        #pragma unroll
        for (int q = 0; q < 4; q++) acc[nt][q] = 0.0f;

    // prologue: stages 0..3
    ISSUE_P(psrc,                              d0,                   d1);
    ISSUE_P(psrc + (size_t)16 * HWP,           d0 + STAGE_BYTES,     d1 + STAGE_BYTES);
    ISSUE_P(psrc + (size_t)32 * HWP,           d0 + 2 * STAGE_BYTES, d1 + 2 * STAGE_BYTES);
    ISSUE_P(psrc + (size_t)48 * HWP,           d0 + 3 * STAGE_BYTES, d1 + 3 * STAGE_BYTES);

    const float* wsrc = psrc + (size_t)64 * HWP;   // stage kt+4 source
    uint32_t soff_w = 4 * STAGE_BYTES;             // ((kt+4)%5)*STAGE_BYTES
    int soff_c = 0;                                // (kt%5)*STAGE_FLOATS
    const uint4* bp = reinterpret_cast<const uint4*>(g_bfrag + (size_t)lane * 16);

    for (int kt = 0; kt < NKT; kt++) {
        asm volatile("cp.async.wait_group 3;" ::: "memory");
        __syncthreads();

        // issue stage kt+4 (slot freed at last barrier); empty commit in tail
        if (kt + 4 < NKT) {
            ISSUE_P(wsrc, d0 + soff_w, d1 + soff_w);
            wsrc += (size_t)16 * HWP;
            soff_w += STAGE_BYTES;
            if (soff_w == STAGES * STAGE_BYTES) soff_w = 0;
        } else {
            asm volatile("cp.async.commit_group;" ::: "memory");
        }

        // consume stage kt
        const float* c = cbase + soff_c;
        float f0 = c[0],          f1 = c[8];            // ch c0
        float f2 = c[ROWW],       f3 = c[ROWW + 8];     // ch c0+1
        float f4 = c[8 * ROWW],   f5 = c[8 * ROWW + 8]; // ch c0+8
        float f6 = c[9 * ROWW],   f7 = c[9 * ROWW + 8]; // ch c0+9
        uint32_t a[4];
        CVT2(a[0], f0, f2);
        CVT2(a[1], f1, f3);
        CVT2(a[2], f4, f6);
        CVT2(a[3], f5, f7);

        uint4 q0 = bp[0], q1 = bp[1], q2 = bp[2], q3 = bp[3];
        MMA16816(acc[0], a, q0.x, q0.y);
        MMA16816(acc[1], a, q0.z, q0.w);
        MMA16816(acc[2], a, q1.x, q1.y);
        MMA16816(acc[3], a, q1.z, q1.w);
        MMA16816(acc[4], a, q2.x, q2.y);
        MMA16816(acc[5], a, q2.z, q2.w);
        MMA16816(acc[6], a, q3.x, q3.y);

        // next ktile's fragment block: 32 lanes x 16 u32 = 128 uint4
        bp += 128;
        soff_c += STAGE_FLOATS;
        if (soff_c == STAGES * STAGE_FLOATS) soff_c = 0;
    }

    // ---- epilogue straight from fragments
    const int l4 = lane >> 2;
    const int l2 = (lane & 3) * 2;
    float bias0[NTILES], bias1[NTILES];
    #pragma unroll
    for (int nt = 0; nt < NTILES; nt++) {
        bias0[nt] = g_bias[nt * 8 + l2];
        bias1[nt] = g_bias[nt * 8 + l2 + 1];
    }

    #pragma unroll
    for (int h = 0; h < 2; h++) {
        int pix = wid * 16 + h * 8 + l4;
        size_t gpix = (size_t)n * HWP + px0 + pix;
        float* lb = out + gpix * 36;
        float* sb = out + SC_BASE + gpix * 18;
        float* fb = out + FG_BASE + gpix * 9;
        #pragma unroll
        for (int nt = 0; nt < NTILES; nt++) {
            int col = nt * 8 + l2;
            float v0 = acc[nt][2 * h]     + bias0[nt];
            float v1 = acc[nt][2 * h + 1] + bias1[nt];
            if (col < 36) {
                *reinterpret_cast<float2*>(lb + col) = make_float2(v0, v1);
            } else if (col < 54) {
                *reinterpret_cast<float2*>(sb + (col - 36)) = make_float2(v0, v1);
                fb[(col - 36) >> 1] = 1.0f / (1.0f + __expf(v0 - v1));
            }
        }
    }
}

// ---------------------------------------------------------------- launch
extern "C" void kernel_launch(void* const* d_in, const int* in_sizes, int n_in,
                              void* d_out, int out_size) {
    (void)in_sizes; (void)n_in; (void)out_size;
    const float* x       = (const float*)d_in[0];
    const float* loc_w   = (const float*)d_in[1];
    const float* loc_b   = (const float*)d_in[2];
    const float* score_w = (const float*)d_in[3];
    const float* score_b = (const float*)d_in[4];
    float* out = (float*)d_out;

    pack_w_kernel<<<(HWP * 9 + 255) / 256, 256>>>(
        loc_w, loc_b, score_w, score_b, out + ANCH_BASE);

    rpn_hmma_kernel<<<NB * TILES_PER_IMG, 256>>>(x, out);
}